// round 11
// baseline (speedup 1.0000x reference)
#include <cuda_runtime.h>
#include <cuda_fp16.h>
#include <cstdint>
#include <cstddef>

#define D 128
#define MAXN 50000
#define MAXE 800000
#define BN_EPS 1e-5f
#define TGRID 296                              // 2 persistent CTAs per SM

// ---------------- device scratch (zero-initialized at module load; every kernel
// that consumes a counter restores it to zero for the next replay) ----------------
__device__ __half2 g_x16[(size_t)MAXN * 64];    // fp16 x; reused as rbh after layer 1
__device__ __half2 g_h16[(size_t)MAXN * 64];    // fp16 h
__device__ __half2 g_agg16[(size_t)MAXN * 64];  // fp16 neighbor mean
__device__ __half2 g_bf1[16 * 16 * 32 * 2];     // layer-1 B fragments
__device__ __half2 g_bf2[16 * 16 * 32 * 2];     // layer-2 B fragments
__device__ int    g_cnt[MAXN];                  // zeroed by scan_k after use
__device__ int    g_offs[MAXN + 1];
__device__ int    g_cur[MAXN];
__device__ int    g_esrc[MAXE];
__device__ int    g_done;                       // zeroed by stats_k last block
__device__ float  g_colsum[D], g_colsumsq[D];   // zeroed by stats_k last block
__device__ float  g_scale[D], g_shift[D];

// ---------------- helpers ----------------
__device__ __forceinline__ void red_add1(float* p, float v) {
    asm volatile("red.global.add.f32 [%0], %1;" :: "l"(p), "f"(v) : "memory");
}
__device__ __forceinline__ void mma16816(float* c, uint32_t a0, uint32_t a1,
                                         uint32_t a2, uint32_t a3,
                                         uint32_t b0, uint32_t b1) {
    asm volatile("mma.sync.aligned.m16n8k16.row.col.f32.f16.f16.f32 "
                 "{%0,%1,%2,%3}, {%4,%5,%6,%7}, {%8,%9}, {%0,%1,%2,%3};"
                 : "+f"(c[0]), "+f"(c[1]), "+f"(c[2]), "+f"(c[3])
                 : "r"(a0), "r"(a1), "r"(a2), "r"(a3), "r"(b0), "r"(b1));
}

// ---------------- fused setup: B fragments + conv x->fp16 + degree histogram ----
// block partition: [0, 64) bfrag | [64, 64+cb) conv | [64+cb, ...) hist
__global__ void setup_k(const float* __restrict__ x,
                        const float* __restrict__ w1l, const float* __restrict__ w1r,
                        const float* __restrict__ w2l, const float* __restrict__ w2r,
                        const int* __restrict__ ei, int N, int E, int cb) {
    int b = blockIdx.x, t = threadIdx.x;
    if (b < 64) {
        // B fragment precompute: m16n8k16 B frag, lane t%32 holds
        // {B[k0+2(t%4)][n], B[k0+2(t%4)+1][n]} and same at k+8; n = nt*8 + t/4
        int idx = b * 256 + t;               // 0..16383
        int layer = idx >> 13;
        int slot  = idx & 8191;              // (ks*16+nt)*32 + lane
        int lane  = slot & 31;
        int fk    = slot >> 5;
        int ks = fk >> 4, nt = fk & 15;
        int n  = nt * 8 + (lane >> 2);
        int k0 = ks * 16 + 2 * (lane & 3);
        const float* wl = layer ? w2l : w1l;
        const float* wr = layer ? w2r : w1r;
        auto W = [&](int k) { return (k < 128) ? wl[n * 128 + k] : wr[n * 128 + k - 128]; };
        __half2* dst = (layer ? g_bf2 : g_bf1) + (size_t)slot * 2;
        dst[0] = __floats2half2_rn(W(k0),     W(k0 + 1));
        dst[1] = __floats2half2_rn(W(k0 + 8), W(k0 + 9));
        return;
    }
    if (b < 64 + cb) {
        int i = (b - 64) * 256 + t;          // float4 index over x
        if (i >= N * 32) return;
        float4 v = __ldg((const float4*)x + i);
        g_x16[(size_t)i * 2]     = __floats2half2_rn(v.x, v.y);
        g_x16[(size_t)i * 2 + 1] = __floats2half2_rn(v.z, v.w);
        return;
    }
    int e = (b - 64 - cb) * 256 + t;         // edge index (histogram)
    if (e < E) atomicAdd(&g_cnt[ei[E + e]], 1);
}

// ---------------- single-block scan: cnt -> offs/cur (+ cnt reset) ---------------
// 1024 threads; thread t owns contiguous chunk [t*chunk, t*chunk+chunk)
__global__ void __launch_bounds__(1024, 1)
scan_k(int n, int E) {
    __shared__ int warpTot[32];
    int t = threadIdx.x;
    int lane = t & 31, wid = t >> 5;
    int chunk = (n + 1023) >> 10;
    int beg = t * chunk;
    int end = min(beg + chunk, n);
    int sum = 0;
    for (int i = beg; i < end; i++) sum += g_cnt[i];
    // block-wide exclusive scan of per-thread sums (warp shuffle)
    int v = sum;
    #pragma unroll
    for (int off = 1; off < 32; off <<= 1) {
        int u = __shfl_up_sync(0xffffffffu, v, off);
        if (lane >= off) v += u;
    }
    if (lane == 31) warpTot[wid] = v;
    __syncthreads();
    if (wid == 0) {
        int w = warpTot[lane];
        #pragma unroll
        for (int off = 1; off < 32; off <<= 1) {
            int u = __shfl_up_sync(0xffffffffu, w, off);
            if (lane >= off) w += u;
        }
        warpTot[lane] = w;                   // inclusive warp totals
    }
    __syncthreads();
    int run = (v - sum) + (wid ? warpTot[wid - 1] : 0);   // exclusive prefix
    for (int i = beg; i < end; i++) {
        int c = g_cnt[i];
        g_cnt[i] = 0;                        // reset for next replay
        g_offs[i] = run;
        g_cur[i] = run;
        run += c;
    }
    if (t == 0) g_offs[n] = E;
}

__global__ void fill_k(const int* __restrict__ ei, int E) {
    int e = blockIdx.x * blockDim.x + threadIdx.x;
    if (e < E) {
        int d = ei[E + e];
        int pos = atomicAdd(&g_cur[d], 1);
        g_esrc[pos] = ei[e];
    }
}

// ---------------- gather: one warp per node, LDG.64 per edge per lane -----------
// BN variant applies relu(bn(.)) per neighbor (pre-mean, fp32) and also writes
// this node's relu(bn(h)) row to rbh for the transform's self path.
template<bool BN>
__global__ void gather_k(const __half2* __restrict__ feat, uint2* __restrict__ rbh,
                         int N) {
    int gw = (blockIdx.x * blockDim.x + threadIdx.x) >> 5;
    int lane = threadIdx.x & 31;
    if (gw >= N) return;
    int s0 = g_offs[gw], s1 = g_offs[gw + 1];
    float4 sc, sh;
    if (BN) {
        sc = ((const float4*)g_scale)[lane];
        sh = ((const float4*)g_shift)[lane];
    }
    const uint2* f = (const uint2*)feat;            // row = 32 uint2 (256B)
    float4 acc = make_float4(0.f, 0.f, 0.f, 0.f);
    int e = s0;
    for (; e + 2 <= s1; e += 2) {
        int a = g_esrc[e], b = g_esrc[e + 1];
        uint2 va = __ldg(f + (size_t)a * 32 + lane);
        uint2 vb = __ldg(f + (size_t)b * 32 + lane);
        float2 fa0 = __half22float2(*(__half2*)&va.x);
        float2 fa1 = __half22float2(*(__half2*)&va.y);
        float2 fb0 = __half22float2(*(__half2*)&vb.x);
        float2 fb1 = __half22float2(*(__half2*)&vb.y);
        if (BN) {
            fa0.x = fmaxf(fmaf(fa0.x, sc.x, sh.x), 0.f);
            fa0.y = fmaxf(fmaf(fa0.y, sc.y, sh.y), 0.f);
            fa1.x = fmaxf(fmaf(fa1.x, sc.z, sh.z), 0.f);
            fa1.y = fmaxf(fmaf(fa1.y, sc.w, sh.w), 0.f);
            fb0.x = fmaxf(fmaf(fb0.x, sc.x, sh.x), 0.f);
            fb0.y = fmaxf(fmaf(fb0.y, sc.y, sh.y), 0.f);
            fb1.x = fmaxf(fmaf(fb1.x, sc.z, sh.z), 0.f);
            fb1.y = fmaxf(fmaf(fb1.y, sc.w, sh.w), 0.f);
        }
        acc.x += fa0.x + fb0.x; acc.y += fa0.y + fb0.y;
        acc.z += fa1.x + fb1.x; acc.w += fa1.y + fb1.y;
    }
    if (e < s1) {
        int a = g_esrc[e];
        uint2 va = __ldg(f + (size_t)a * 32 + lane);
        float2 fa0 = __half22float2(*(__half2*)&va.x);
        float2 fa1 = __half22float2(*(__half2*)&va.y);
        if (BN) {
            fa0.x = fmaxf(fmaf(fa0.x, sc.x, sh.x), 0.f);
            fa0.y = fmaxf(fmaf(fa0.y, sc.y, sh.y), 0.f);
            fa1.x = fmaxf(fmaf(fa1.x, sc.z, sh.z), 0.f);
            fa1.y = fmaxf(fmaf(fa1.y, sc.w, sh.w), 0.f);
        }
        acc.x += fa0.x; acc.y += fa0.y; acc.z += fa1.x; acc.w += fa1.y;
    }
    float inv = 1.0f / fmaxf((float)(s1 - s0), 1.0f);
    uint2 o;
    *(__half2*)&o.x = __floats2half2_rn(acc.x * inv, acc.y * inv);
    *(__half2*)&o.y = __floats2half2_rn(acc.z * inv, acc.w * inv);
    ((uint2*)g_agg16)[(size_t)gw * 32 + lane] = o;
    if (BN) {
        // materialize this node's relu(bn(h)) row for the self path
        uint2 vs = __ldg(f + (size_t)gw * 32 + lane);
        float2 s0f = __half22float2(*(__half2*)&vs.x);
        float2 s1f = __half22float2(*(__half2*)&vs.y);
        s0f.x = fmaxf(fmaf(s0f.x, sc.x, sh.x), 0.f);
        s0f.y = fmaxf(fmaf(s0f.y, sc.y, sh.y), 0.f);
        s1f.x = fmaxf(fmaf(s1f.x, sc.z, sh.z), 0.f);
        s1f.y = fmaxf(fmaf(s1f.y, sc.w, sh.w), 0.f);
        uint2 so;
        *(__half2*)&so.x = __floats2half2_rn(s0f.x, s0f.y);
        *(__half2*)&so.y = __floats2half2_rn(s1f.x, s1f.y);
        rbh[(size_t)gw * 32 + lane] = so;
    }
}

// ---------------- HMMA node transform ----------------
template<bool OUT_HALF>
__global__ void __launch_bounds__(256, 2)
mma_transform_k(const uint32_t* __restrict__ aggH,   // [m][64] half2-as-u32
                const uint32_t* __restrict__ selfH,
                const uint2* __restrict__ bfrag,     // 8192 x 8B fragments
                const float* __restrict__ bias,
                float* __restrict__ outF, __half2* __restrict__ outH,
                int nNodes, int ntiles) {
    extern __shared__ char smraw[];
    uint2* sB = (uint2*)smraw;                        // 64KB
    float* sBias = (float*)(smraw + 65536);
    int tid = threadIdx.x;
    for (int i = tid; i < 8192; i += 256) sB[i] = __ldg(bfrag + i);
    if (tid < 128) sBias[tid] = __ldg(bias + tid);
    __syncthreads();

    int warp = tid >> 5, lane = tid & 31;
    int r = lane >> 2, c = lane & 3;

    for (int tile = blockIdx.x; tile < ntiles; tile += gridDim.x) {
        int m0 = tile * 128 + warp * 16;
        size_t row0 = (size_t)min(m0 + r,     nNodes - 1);
        size_t row1 = (size_t)min(m0 + r + 8, nNodes - 1);
        const uint32_t* p0a = aggH  + row0 * 64 + c;
        const uint32_t* p1a = aggH  + row1 * 64 + c;
        const uint32_t* p0s = selfH + row0 * 64 + c;
        const uint32_t* p1s = selfH + row1 * 64 + c;

        float acc[16][4];
        #pragma unroll
        for (int nt = 0; nt < 16; nt++)
            #pragma unroll
            for (int q = 0; q < 4; q++) acc[nt][q] = 0.f;

        #pragma unroll
        for (int ks = 0; ks < 16; ks++) {
            const uint32_t* p0 = (ks < 8) ? p0a + ks * 8 : p0s + (ks - 8) * 8;
            const uint32_t* p1 = (ks < 8) ? p1a + ks * 8 : p1s + (ks - 8) * 8;
            uint32_t a0 = __ldg(p0), a2 = __ldg(p0 + 4);
            uint32_t a1 = __ldg(p1), a3 = __ldg(p1 + 4);
            const uint2* bp = sB + ks * 512 + lane;
            #pragma unroll
            for (int nt = 0; nt < 16; nt++) {
                uint2 b = bp[nt * 32];
                mma16816(acc[nt], a0, a1, a2, a3, b.x, b.y);
            }
        }

        bool ok0 = (m0 + r)     < nNodes;
        bool ok1 = (m0 + r + 8) < nNodes;
        #pragma unroll
        for (int nt = 0; nt < 16; nt++) {
            int j = nt * 8 + 2 * c;
            float b0 = sBias[j], b1 = sBias[j + 1];
            float v0 = acc[nt][0] + b0, v1 = acc[nt][1] + b1;
            float v2 = acc[nt][2] + b0, v3 = acc[nt][3] + b1;
            if (OUT_HALF) {
                if (ok0) outH[(size_t)(m0 + r)     * 64 + (j >> 1)] = __floats2half2_rn(v0, v1);
                if (ok1) outH[(size_t)(m0 + r + 8) * 64 + (j >> 1)] = __floats2half2_rn(v2, v3);
            } else {
                if (ok0) *(float2*)(outF + (size_t)(m0 + r)     * 128 + j) = make_float2(v0, v1);
                if (ok1) *(float2*)(outF + (size_t)(m0 + r + 8) * 128 + j) = make_float2(v2, v3);
            }
        }
    }
}

// ---------------- BN stats + finalize (last-block), self-resetting --------------
__global__ void stats_k(const float* __restrict__ gamma,
                        const float* __restrict__ beta, float invN, int N) {
    int c2  = threadIdx.x & 63;
    int sub = threadIdx.x >> 6;      // 0..3
    float sx = 0.f, sy = 0.f, qx = 0.f, qy = 0.f;
    for (int row = blockIdx.x * 4 + sub; row < N; row += gridDim.x * 4) {
        float2 f = __half22float2(g_h16[(size_t)row * 64 + c2]);
        sx += f.x; sy += f.y; qx += f.x * f.x; qy += f.y * f.y;
    }
    red_add1(g_colsum   + 2 * c2,     sx);
    red_add1(g_colsum   + 2 * c2 + 1, sy);
    red_add1(g_colsumsq + 2 * c2,     qx);
    red_add1(g_colsumsq + 2 * c2 + 1, qy);
    __threadfence();
    __shared__ int isLast;
    __syncthreads();
    if (threadIdx.x == 0)
        isLast = (atomicAdd(&g_done, 1) == gridDim.x - 1);
    __syncthreads();
    if (isLast && threadIdx.x < 128) {
        int j = threadIdx.x;
        float mu  = __ldcg(g_colsum + j) * invN;
        float var = __ldcg(g_colsumsq + j) * invN - mu * mu;
        float sc  = __ldg(gamma + j) * rsqrtf(var + BN_EPS);
        g_scale[j] = sc;
        g_shift[j] = fmaf(-mu, sc, __ldg(beta + j));
        g_colsum[j] = 0.f;           // reset for next replay
        g_colsumsq[j] = 0.f;
        if (j == 0) g_done = 0;
    }
}

// ---------------- launch ----------------
extern "C" void kernel_launch(void* const* d_in, const int* in_sizes, int n_in,
                              void* d_out, int out_size) {
    const float* x     = (const float*)d_in[0];
    const int*   ei    = (const int*)d_in[1];     // int32
    const float* w1l   = (const float*)d_in[2];
    const float* b1l   = (const float*)d_in[3];
    const float* w1r   = (const float*)d_in[4];
    const float* w2l   = (const float*)d_in[5];
    const float* b2l   = (const float*)d_in[6];
    const float* w2r   = (const float*)d_in[7];
    const float* gamma = (const float*)d_in[8];
    const float* beta  = (const float*)d_in[9];
    float*       out   = (float*)d_out;

    int N = in_sizes[0] / D;
    int E = in_sizes[1] / 2;
    int ntiles = (N + 127) / 128;

    void *p_x16, *p_h16, *p_agg16, *p_bf1, *p_bf2;
    cudaGetSymbolAddress(&p_x16,   g_x16);
    cudaGetSymbolAddress(&p_h16,   g_h16);
    cudaGetSymbolAddress(&p_agg16, g_agg16);
    cudaGetSymbolAddress(&p_bf1,   g_bf1);
    cudaGetSymbolAddress(&p_bf2,   g_bf2);

    int smem = 65536 + 512;
    cudaFuncSetAttribute(mma_transform_k<true>,
                         cudaFuncAttributeMaxDynamicSharedMemorySize, smem);
    cudaFuncSetAttribute(mma_transform_k<false>,
                         cudaFuncAttributeMaxDynamicSharedMemorySize, smem);

    // fused setup: 64 bfrag blocks + cb conv blocks + egrid hist blocks
    int cb = (N * 32 + 255) / 256;
    int egrid = (E + 255) / 256;
    setup_k<<<64 + cb + egrid, 256>>>(x, w1l, w1r, w2l, w2r, ei, N, E, cb);

    // CSR: single-block scan, then fill
    scan_k<<<1, 1024>>>(N, E);
    fill_k<<<egrid, 256>>>(ei, E);

    int ggrid = (N * 32 + 255) / 256;

    // layer 1: h = mean(x_nbr)@W1l + b1 + x@W1r   (fp16 inputs, fp32 acc)
    gather_k<false><<<ggrid, 256>>>((const __half2*)p_x16, nullptr, N);
    mma_transform_k<true><<<TGRID, 256, smem>>>(
        (const uint32_t*)p_agg16, (const uint32_t*)p_x16,
        (const uint2*)p_bf1, b1l, nullptr, (__half2*)p_h16, N, ntiles);

    // BN stats + finalize (fused, self-resetting)
    stats_k<<<148, 256>>>(gamma, beta, 1.0f / (float)N, N);

    // layer 2: gather applies relu(bn(.)) pre-mean and writes rbh (reuses g_x16)
    gather_k<true><<<ggrid, 256>>>((const __half2*)p_h16, (uint2*)p_x16, N);
    mma_transform_k<false><<<TGRID, 256, smem>>>(
        (const uint32_t*)p_agg16, (const uint32_t*)p_x16,
        (const uint2*)p_bf2, b2l, out, nullptr, N, ntiles);
}

// round 12
// speedup vs baseline: 1.5442x; 1.5442x over previous
#include <cuda_runtime.h>
#include <cuda_fp16.h>
#include <cstdint>
#include <cstddef>

#define D 128
#define MAXN 50000
#define MAXE 800000
#define BN_EPS 1e-5f
#define SCAN_B 1024
#define NBLK ((MAXN + SCAN_B - 1) / SCAN_B)   // 49
#define TGRID 296                              // 2 persistent CTAs per SM

// ---------------- device scratch ----------------
__device__ __half2 g_x16[(size_t)MAXN * 64];    // fp16 x
__device__ __half2 g_h16[(size_t)MAXN * 64];    // fp16 h (relu(bn(h)) in place later)
__device__ __half2 g_agg16[(size_t)MAXN * 64];  // fp16 neighbor mean
__device__ __half2 g_bf1[16 * 16 * 32 * 2];     // layer-1 B fragments
__device__ __half2 g_bf2[16 * 16 * 32 * 2];     // layer-2 B fragments
__device__ int    g_cnt[MAXN];
__device__ int    g_offs[MAXN + 1];
__device__ int    g_cur[MAXN];
__device__ int    g_bsum[NBLK];
__device__ int    g_esrc[MAXE];
__device__ int    g_done;
__device__ float  g_colsum[D], g_colsumsq[D], g_scale[D], g_shift[D];

// ---------------- helpers ----------------
__device__ __forceinline__ void red_add1(float* p, float v) {
    asm volatile("red.global.add.f32 [%0], %1;" :: "l"(p), "f"(v) : "memory");
}
__device__ __forceinline__ void mma16816(float* c, uint32_t a0, uint32_t a1,
                                         uint32_t a2, uint32_t a3,
                                         uint32_t b0, uint32_t b1) {
    asm volatile("mma.sync.aligned.m16n8k16.row.col.f32.f16.f16.f32 "
                 "{%0,%1,%2,%3}, {%4,%5,%6,%7}, {%8,%9}, {%0,%1,%2,%3};"
                 : "+f"(c[0]), "+f"(c[1]), "+f"(c[2]), "+f"(c[3])
                 : "r"(a0), "r"(a1), "r"(a2), "r"(a3), "r"(b0), "r"(b1));
}

// ---------------- fused setup: zero scratch + conv x->fp16 + B fragments ---------
// block partition: [0, zb) zero | [zb, zb+64) bfrag | [zb+64, ...) conv
__global__ void setup_k(const float* __restrict__ x,
                        const float* __restrict__ w1l, const float* __restrict__ w1r,
                        const float* __restrict__ w2l, const float* __restrict__ w2r,
                        int N, int zb) {
    int b = blockIdx.x, t = threadIdx.x;
    if (b < zb) {
        int i = b * 256 + t;
        if (i < N) g_cnt[i] = 0;
        else if (i < N + 128) g_colsum[i - N] = 0.f;
        else if (i < N + 256) g_colsumsq[i - N - 128] = 0.f;
        else if (i == N + 256) g_done = 0;
        return;
    }
    if (b < zb + 64) {
        // B fragment precompute: m16n8k16 B frag, lane t%32 holds
        // {B[k0+2(t%4)][n], B[k0+2(t%4)+1][n]} and same at k+8; n = nt*8 + t/4
        int idx = (b - zb) * 256 + t;        // 0..16383
        int layer = idx >> 13;
        int slot  = idx & 8191;              // (ks*16+nt)*32 + lane
        int lane  = slot & 31;
        int fk    = slot >> 5;
        int ks = fk >> 4, nt = fk & 15;
        int n  = nt * 8 + (lane >> 2);
        int k0 = ks * 16 + 2 * (lane & 3);
        const float* wl = layer ? w2l : w1l;
        const float* wr = layer ? w2r : w1r;
        auto W = [&](int k) { return (k < 128) ? wl[n * 128 + k] : wr[n * 128 + k - 128]; };
        __half2* dst = (layer ? g_bf2 : g_bf1) + (size_t)slot * 2;
        dst[0] = __floats2half2_rn(W(k0),     W(k0 + 1));
        dst[1] = __floats2half2_rn(W(k0 + 8), W(k0 + 9));
        return;
    }
    int i = (b - zb - 64) * 256 + t;         // float4 index over x
    if (i >= N * 32) return;
    float4 v = __ldg((const float4*)x + i);
    g_x16[(size_t)i * 2]     = __floats2half2_rn(v.x, v.y);
    g_x16[(size_t)i * 2 + 1] = __floats2half2_rn(v.z, v.w);
}

// ---------------- CSR build ----------------
__global__ void hist_k(const int* __restrict__ ei, int E) {
    int e = blockIdx.x * blockDim.x + threadIdx.x;
    if (e < E) atomicAdd(&g_cnt[ei[E + e]], 1);
}

__global__ void scan_local_k(int n) {
    __shared__ int sm[SCAN_B];
    int t = threadIdx.x, i = blockIdx.x * SCAN_B + t;
    int v = (i < n) ? g_cnt[i] : 0;
    sm[t] = v; __syncthreads();
    int acc = v;
    #pragma unroll
    for (int off = 1; off < SCAN_B; off <<= 1) {
        int add = (t >= off) ? sm[t - off] : 0;
        __syncthreads();
        acc += add; sm[t] = acc;
        __syncthreads();
    }
    if (i < n) g_offs[i] = acc - v;
    if (t == SCAN_B - 1) g_bsum[blockIdx.x] = acc;
}

// scan_add with the 49-entry block-sum scan done redundantly per block
__global__ void scan_add_k(int n, int E) {
    __shared__ int sb[64];
    int t = threadIdx.x;
    int orig = 0;
    if (t < 64) { orig = (t < NBLK) ? g_bsum[t] : 0; sb[t] = orig; }
    __syncthreads();
    #pragma unroll
    for (int off = 1; off < 64; off <<= 1) {
        int add = 0;
        if (t < 64 && t >= off) add = sb[t - off];
        __syncthreads();
        if (t < 64) sb[t] += add;
        __syncthreads();
    }
    if (t < 64) sb[t] -= orig;        // inclusive -> exclusive
    __syncthreads();
    int i = blockIdx.x * blockDim.x + t;
    if (i < n) {
        int o = g_offs[i] + sb[i >> 10];    // SCAN_B = 1024
        g_offs[i] = o;
        g_cur[i] = o;
    }
    if (i == n) g_offs[n] = E;
}

__global__ void fill_k(const int* __restrict__ ei, int E) {
    int e = blockIdx.x * blockDim.x + threadIdx.x;
    if (e < E) {
        int d = ei[E + e];
        int pos = atomicAdd(&g_cur[d], 1);
        g_esrc[pos] = ei[e];
    }
}

// ---------------- gather: one warp per node, 4-way edge ILP -----------------------
__global__ void gather_k(const __half2* __restrict__ feat, int N) {
    int gw = (blockIdx.x * blockDim.x + threadIdx.x) >> 5;
    int lane = threadIdx.x & 31;
    if (gw >= N) return;
    int s0 = g_offs[gw], s1 = g_offs[gw + 1];
    const uint2* f = (const uint2*)feat;            // row = 32 uint2 (256B)
    float4 acc = make_float4(0.f, 0.f, 0.f, 0.f);
    int e = s0;
    for (; e + 4 <= s1; e += 4) {
        int i0 = g_esrc[e],     i1 = g_esrc[e + 1];
        int i2 = g_esrc[e + 2], i3 = g_esrc[e + 3];
        uint2 v0 = __ldg(f + (size_t)i0 * 32 + lane);
        uint2 v1 = __ldg(f + (size_t)i1 * 32 + lane);
        uint2 v2 = __ldg(f + (size_t)i2 * 32 + lane);
        uint2 v3 = __ldg(f + (size_t)i3 * 32 + lane);
        float2 a0 = __half22float2(*(__half2*)&v0.x);
        float2 a1 = __half22float2(*(__half2*)&v0.y);
        float2 b0 = __half22float2(*(__half2*)&v1.x);
        float2 b1 = __half22float2(*(__half2*)&v1.y);
        float2 c0 = __half22float2(*(__half2*)&v2.x);
        float2 c1 = __half22float2(*(__half2*)&v2.y);
        float2 d0 = __half22float2(*(__half2*)&v3.x);
        float2 d1 = __half22float2(*(__half2*)&v3.y);
        acc.x += (a0.x + b0.x) + (c0.x + d0.x);
        acc.y += (a0.y + b0.y) + (c0.y + d0.y);
        acc.z += (a1.x + b1.x) + (c1.x + d1.x);
        acc.w += (a1.y + b1.y) + (c1.y + d1.y);
    }
    for (; e < s1; e++) {
        int a = g_esrc[e];
        uint2 va = __ldg(f + (size_t)a * 32 + lane);
        float2 fa0 = __half22float2(*(__half2*)&va.x);
        float2 fa1 = __half22float2(*(__half2*)&va.y);
        acc.x += fa0.x; acc.y += fa0.y; acc.z += fa1.x; acc.w += fa1.y;
    }
    float inv = 1.0f / fmaxf((float)(s1 - s0), 1.0f);
    uint2 o;
    *(__half2*)&o.x = __floats2half2_rn(acc.x * inv, acc.y * inv);
    *(__half2*)&o.y = __floats2half2_rn(acc.z * inv, acc.w * inv);
    ((uint2*)g_agg16)[(size_t)gw * 32 + lane] = o;
}

// ---------------- HMMA node transform ----------------
template<bool OUT_HALF>
__global__ void __launch_bounds__(256, 2)
mma_transform_k(const uint32_t* __restrict__ aggH,   // [m][64] half2-as-u32
                const uint32_t* __restrict__ selfH,
                const uint2* __restrict__ bfrag,     // 8192 x 8B fragments
                const float* __restrict__ bias,
                float* __restrict__ outF, __half2* __restrict__ outH,
                int nNodes, int ntiles) {
    extern __shared__ char smraw[];
    uint2* sB = (uint2*)smraw;                        // 64KB
    float* sBias = (float*)(smraw + 65536);
    int tid = threadIdx.x;
    for (int i = tid; i < 8192; i += 256) sB[i] = __ldg(bfrag + i);
    if (tid < 128) sBias[tid] = __ldg(bias + tid);
    __syncthreads();

    int warp = tid >> 5, lane = tid & 31;
    int r = lane >> 2, c = lane & 3;

    for (int tile = blockIdx.x; tile < ntiles; tile += gridDim.x) {
        int m0 = tile * 128 + warp * 16;
        size_t row0 = (size_t)min(m0 + r,     nNodes - 1);
        size_t row1 = (size_t)min(m0 + r + 8, nNodes - 1);
        const uint32_t* p0a = aggH  + row0 * 64 + c;
        const uint32_t* p1a = aggH  + row1 * 64 + c;
        const uint32_t* p0s = selfH + row0 * 64 + c;
        const uint32_t* p1s = selfH + row1 * 64 + c;

        float acc[16][4];
        #pragma unroll
        for (int nt = 0; nt < 16; nt++)
            #pragma unroll
            for (int q = 0; q < 4; q++) acc[nt][q] = 0.f;

        #pragma unroll
        for (int ks = 0; ks < 16; ks++) {
            const uint32_t* p0 = (ks < 8) ? p0a + ks * 8 : p0s + (ks - 8) * 8;
            const uint32_t* p1 = (ks < 8) ? p1a + ks * 8 : p1s + (ks - 8) * 8;
            uint32_t a0 = __ldg(p0), a2 = __ldg(p0 + 4);
            uint32_t a1 = __ldg(p1), a3 = __ldg(p1 + 4);
            const uint2* bp = sB + ks * 512 + lane;
            #pragma unroll
            for (int nt = 0; nt < 16; nt++) {
                uint2 b = bp[nt * 32];
                mma16816(acc[nt], a0, a1, a2, a3, b.x, b.y);
            }
        }

        bool ok0 = (m0 + r)     < nNodes;
        bool ok1 = (m0 + r + 8) < nNodes;
        #pragma unroll
        for (int nt = 0; nt < 16; nt++) {
            int j = nt * 8 + 2 * c;
            float b0 = sBias[j], b1 = sBias[j + 1];
            float v0 = acc[nt][0] + b0, v1 = acc[nt][1] + b1;
            float v2 = acc[nt][2] + b0, v3 = acc[nt][3] + b1;
            if (OUT_HALF) {
                if (ok0) outH[(size_t)(m0 + r)     * 64 + (j >> 1)] = __floats2half2_rn(v0, v1);
                if (ok1) outH[(size_t)(m0 + r + 8) * 64 + (j >> 1)] = __floats2half2_rn(v2, v3);
            } else {
                if (ok0) *(float2*)(outF + (size_t)(m0 + r)     * 128 + j) = make_float2(v0, v1);
                if (ok1) *(float2*)(outF + (size_t)(m0 + r + 8) * 128 + j) = make_float2(v2, v3);
            }
        }
    }
}

// ---------------- BN stats + finalize (last-block pattern) ----------------
__global__ void stats_k(const float* __restrict__ gamma,
                        const float* __restrict__ beta, float invN, int N) {
    int c2  = threadIdx.x & 63;
    int sub = threadIdx.x >> 6;      // 0..3
    float sx = 0.f, sy = 0.f, qx = 0.f, qy = 0.f;
    for (int row = blockIdx.x * 4 + sub; row < N; row += gridDim.x * 4) {
        float2 f = __half22float2(g_h16[(size_t)row * 64 + c2]);
        sx += f.x; sy += f.y; qx += f.x * f.x; qy += f.y * f.y;
    }
    red_add1(g_colsum   + 2 * c2,     sx);
    red_add1(g_colsum   + 2 * c2 + 1, sy);
    red_add1(g_colsumsq + 2 * c2,     qx);
    red_add1(g_colsumsq + 2 * c2 + 1, qy);
    __threadfence();
    __shared__ int isLast;
    __syncthreads();
    if (threadIdx.x == 0)
        isLast = (atomicAdd(&g_done, 1) == gridDim.x - 1);
    __syncthreads();
    if (isLast && threadIdx.x < 128) {
        int j = threadIdx.x;
        float mu  = __ldcg(g_colsum + j) * invN;
        float var = __ldcg(g_colsumsq + j) * invN - mu * mu;
        float sc  = __ldg(gamma + j) * rsqrtf(var + BN_EPS);
        g_scale[j] = sc;
        g_shift[j] = fmaf(-mu, sc, __ldg(beta + j));
    }
}

// ---------------- relu(bn(h)) in place on fp16 h ----------------
__global__ void relu_bn_k(int total2) {
    int i = blockIdx.x * blockDim.x + threadIdx.x;
    if (i >= total2) return;
    int c2 = i & 63;
    float2 sc = ((const float2*)g_scale)[c2];
    float2 sh = ((const float2*)g_shift)[c2];
    float2 f = __half22float2(g_h16[i]);
    f.x = fmaxf(fmaf(f.x, sc.x, sh.x), 0.f);
    f.y = fmaxf(fmaf(f.y, sc.y, sh.y), 0.f);
    g_h16[i] = __floats2half2_rn(f.x, f.y);
}

// ---------------- launch ----------------
extern "C" void kernel_launch(void* const* d_in, const int* in_sizes, int n_in,
                              void* d_out, int out_size) {
    const float* x     = (const float*)d_in[0];
    const int*   ei    = (const int*)d_in[1];     // int32
    const float* w1l   = (const float*)d_in[2];
    const float* b1l   = (const float*)d_in[3];
    const float* w1r   = (const float*)d_in[4];
    const float* w2l   = (const float*)d_in[5];
    const float* b2l   = (const float*)d_in[6];
    const float* w2r   = (const float*)d_in[7];
    const float* gamma = (const float*)d_in[8];
    const float* beta  = (const float*)d_in[9];
    float*       out   = (float*)d_out;

    int N = in_sizes[0] / D;
    int E = in_sizes[1] / 2;
    int ntiles = (N + 127) / 128;

    void *p_x16, *p_h16, *p_agg16, *p_bf1, *p_bf2;
    cudaGetSymbolAddress(&p_x16,   g_x16);
    cudaGetSymbolAddress(&p_h16,   g_h16);
    cudaGetSymbolAddress(&p_agg16, g_agg16);
    cudaGetSymbolAddress(&p_bf1,   g_bf1);
    cudaGetSymbolAddress(&p_bf2,   g_bf2);

    int smem = 65536 + 512;
    cudaFuncSetAttribute(mma_transform_k<true>,
                         cudaFuncAttributeMaxDynamicSharedMemorySize, smem);
    cudaFuncSetAttribute(mma_transform_k<false>,
                         cudaFuncAttributeMaxDynamicSharedMemorySize, smem);

    // fused setup: zeros (N+257 words) + 64 bfrag blocks + conv blocks
    int zb = (N + 257 + 255) / 256;
    int cb = (N * 32 + 255) / 256;
    setup_k<<<zb + 64 + cb, 256>>>(x, w1l, w1r, w2l, w2r, N, zb);

    // CSR build (reused by both layers)
    int egrid = (E + 255) / 256;
    hist_k<<<egrid, 256>>>(ei, E);
    scan_local_k<<<NBLK, SCAN_B>>>(N);
    scan_add_k<<<(N + 256) / 256, 256>>>(N, E);
    fill_k<<<egrid, 256>>>(ei, E);

    int ggrid = (N * 32 + 255) / 256;

    // layer 1: h = mean(x_nbr)@W1l + b1 + x@W1r   (fp16 inputs, fp32 acc)
    gather_k<<<ggrid, 256>>>((const __half2*)p_x16, N);
    mma_transform_k<true><<<TGRID, 256, smem>>>(
        (const uint32_t*)p_agg16, (const uint32_t*)p_x16,
        (const uint2*)p_bf1, b1l, nullptr, (__half2*)p_h16, N, ntiles);

    // BN stats + finalize (fused), then relu(bn(h)) in place
    stats_k<<<148, 256>>>(gamma, beta, 1.0f / (float)N, N);
    relu_bn_k<<<(N * 64 + 255) / 256, 256>>>(N * 64);

    // layer 2: out = mean(rbh_nbr)@W2l + b2 + rbh@W2r
    gather_k<<<ggrid, 256>>>((const __half2*)p_h16, N);
    mma_transform_k<false><<<TGRID, 256, smem>>>(
        (const uint32_t*)p_agg16, (const uint32_t*)p_h16,
        (const uint2*)p_bf2, b2l, out, nullptr, N, ntiles);
}

// round 13
// speedup vs baseline: 1.5616x; 1.0113x over previous
#include <cuda_runtime.h>
#include <cuda_fp16.h>
#include <cstdint>
#include <cstddef>

#define D 128
#define MAXN 50000
#define MAXE 800000
#define BN_EPS 1e-5f
#define SCAN_B 1024
#define NBLK ((MAXN + SCAN_B - 1) / SCAN_B)   // 49
#define TGRID 296                              // 2 persistent CTAs per SM

// ---------------- device scratch ----------------
__device__ __half2 g_x16[(size_t)MAXN * 64];    // fp16 x
__device__ __half2 g_h16[(size_t)MAXN * 64];    // fp16 h (relu(bn(h)) in place later)
__device__ __half2 g_agg16[(size_t)MAXN * 64];  // fp16 neighbor mean
__device__ __half2 g_bf1[16 * 16 * 32 * 2];     // layer-1 B fragments
__device__ __half2 g_bf2[16 * 16 * 32 * 2];     // layer-2 B fragments
__device__ int    g_cnt[MAXN];
__device__ int    g_offs[MAXN + 1];
__device__ int    g_cur[MAXN];
__device__ int    g_bsum[NBLK];
__device__ int    g_esrc[MAXE];
__device__ int    g_done;
__device__ float  g_colsum[D], g_colsumsq[D], g_scale[D], g_shift[D];

// ---------------- helpers ----------------
__device__ __forceinline__ void red_add1(float* p, float v) {
    asm volatile("red.global.add.f32 [%0], %1;" :: "l"(p), "f"(v) : "memory");
}
__device__ __forceinline__ void mma16816(float* c, uint32_t a0, uint32_t a1,
                                         uint32_t a2, uint32_t a3,
                                         uint32_t b0, uint32_t b1) {
    asm volatile("mma.sync.aligned.m16n8k16.row.col.f32.f16.f16.f32 "
                 "{%0,%1,%2,%3}, {%4,%5,%6,%7}, {%8,%9}, {%0,%1,%2,%3};"
                 : "+f"(c[0]), "+f"(c[1]), "+f"(c[2]), "+f"(c[3])
                 : "r"(a0), "r"(a1), "r"(a2), "r"(a3), "r"(b0), "r"(b1));
}

// ---------------- fused setup: zero scratch + conv x->fp16 + B fragments ---------
// block partition: [0, zb) zero | [zb, zb+64) bfrag | [zb+64, ...) conv
__global__ void setup_k(const float* __restrict__ x,
                        const float* __restrict__ w1l, const float* __restrict__ w1r,
                        const float* __restrict__ w2l, const float* __restrict__ w2r,
                        int N, int zb) {
    int b = blockIdx.x, t = threadIdx.x;
    if (b < zb) {
        int i = b * 256 + t;
        if (i < N) g_cnt[i] = 0;
        else if (i < N + 128) g_colsum[i - N] = 0.f;
        else if (i < N + 256) g_colsumsq[i - N - 128] = 0.f;
        else if (i == N + 256) g_done = 0;
        return;
    }
    if (b < zb + 64) {
        // B fragment precompute: m16n8k16 B frag, lane t%32 holds
        // {B[k0+2(t%4)][n], B[k0+2(t%4)+1][n]} and same at k+8; n = nt*8 + t/4
        int idx = (b - zb) * 256 + t;        // 0..16383
        int layer = idx >> 13;
        int slot  = idx & 8191;              // (ks*16+nt)*32 + lane
        int lane  = slot & 31;
        int fk    = slot >> 5;
        int ks = fk >> 4, nt = fk & 15;
        int n  = nt * 8 + (lane >> 2);
        int k0 = ks * 16 + 2 * (lane & 3);
        const float* wl = layer ? w2l : w1l;
        const float* wr = layer ? w2r : w1r;
        auto W = [&](int k) { return (k < 128) ? wl[n * 128 + k] : wr[n * 128 + k - 128]; };
        __half2* dst = (layer ? g_bf2 : g_bf1) + (size_t)slot * 2;
        dst[0] = __floats2half2_rn(W(k0),     W(k0 + 1));
        dst[1] = __floats2half2_rn(W(k0 + 8), W(k0 + 9));
        return;
    }
    int i = (b - zb - 64) * 256 + t;         // float4 index over x
    if (i >= N * 32) return;
    float4 v = __ldg((const float4*)x + i);
    g_x16[(size_t)i * 2]     = __floats2half2_rn(v.x, v.y);
    g_x16[(size_t)i * 2 + 1] = __floats2half2_rn(v.z, v.w);
}

// ---------------- CSR build ----------------
// hist: 4 edges per thread via int4 (host guarantees E % 4 == 0 on this path)
__global__ void hist4_k(const int* __restrict__ ei, int E) {
    int i = blockIdx.x * blockDim.x + threadIdx.x;
    if (i * 4 >= E) return;
    int4 d = __ldg((const int4*)(ei + E) + i);
    atomicAdd(&g_cnt[d.x], 1);
    atomicAdd(&g_cnt[d.y], 1);
    atomicAdd(&g_cnt[d.z], 1);
    atomicAdd(&g_cnt[d.w], 1);
}
__global__ void hist1_k(const int* __restrict__ ei, int E) {
    int e = blockIdx.x * blockDim.x + threadIdx.x;
    if (e < E) atomicAdd(&g_cnt[ei[E + e]], 1);
}

__global__ void scan_local_k(int n) {
    __shared__ int sm[SCAN_B];
    int t = threadIdx.x, i = blockIdx.x * SCAN_B + t;
    int v = (i < n) ? g_cnt[i] : 0;
    sm[t] = v; __syncthreads();
    int acc = v;
    #pragma unroll
    for (int off = 1; off < SCAN_B; off <<= 1) {
        int add = (t >= off) ? sm[t - off] : 0;
        __syncthreads();
        acc += add; sm[t] = acc;
        __syncthreads();
    }
    if (i < n) g_offs[i] = acc - v;
    if (t == SCAN_B - 1) g_bsum[blockIdx.x] = acc;
}

// scan_add with the 49-entry block-sum scan done redundantly per block
__global__ void scan_add_k(int n, int E) {
    __shared__ int sb[64];
    int t = threadIdx.x;
    int orig = 0;
    if (t < 64) { orig = (t < NBLK) ? g_bsum[t] : 0; sb[t] = orig; }
    __syncthreads();
    #pragma unroll
    for (int off = 1; off < 64; off <<= 1) {
        int add = 0;
        if (t < 64 && t >= off) add = sb[t - off];
        __syncthreads();
        if (t < 64) sb[t] += add;
        __syncthreads();
    }
    if (t < 64) sb[t] -= orig;        // inclusive -> exclusive
    __syncthreads();
    int i = blockIdx.x * blockDim.x + t;
    if (i < n) {
        int o = g_offs[i] + sb[i >> 10];    // SCAN_B = 1024
        g_offs[i] = o;
        g_cur[i] = o;
    }
    if (i == n) g_offs[n] = E;
}

// fill: 4 edges per thread via int4 (host guarantees E % 4 == 0 on this path)
__global__ void fill4_k(const int* __restrict__ ei, int E) {
    int i = blockIdx.x * blockDim.x + threadIdx.x;
    if (i * 4 >= E) return;
    int4 s = __ldg((const int4*)ei + i);
    int4 d = __ldg((const int4*)(ei + E) + i);
    g_esrc[atomicAdd(&g_cur[d.x], 1)] = s.x;
    g_esrc[atomicAdd(&g_cur[d.y], 1)] = s.y;
    g_esrc[atomicAdd(&g_cur[d.z], 1)] = s.z;
    g_esrc[atomicAdd(&g_cur[d.w], 1)] = s.w;
}
__global__ void fill1_k(const int* __restrict__ ei, int E) {
    int e = blockIdx.x * blockDim.x + threadIdx.x;
    if (e < E) {
        int d = ei[E + e];
        int pos = atomicAdd(&g_cur[d], 1);
        g_esrc[pos] = ei[e];
    }
}

// ---------------- gather: one warp per node, 4-way ILP + fp16 pair-add ----------
__global__ void gather_k(const __half2* __restrict__ feat, int N) {
    int gw = (blockIdx.x * blockDim.x + threadIdx.x) >> 5;
    int lane = threadIdx.x & 31;
    if (gw >= N) return;
    int s0 = g_offs[gw], s1 = g_offs[gw + 1];
    const uint2* f = (const uint2*)feat;            // row = 32 uint2 (256B)
    float4 acc = make_float4(0.f, 0.f, 0.f, 0.f);
    int e = s0;
    for (; e + 4 <= s1; e += 4) {
        int i0 = g_esrc[e],     i1 = g_esrc[e + 1];
        int i2 = g_esrc[e + 2], i3 = g_esrc[e + 3];
        uint2 v0 = __ldg(f + (size_t)i0 * 32 + lane);
        uint2 v1 = __ldg(f + (size_t)i1 * 32 + lane);
        uint2 v2 = __ldg(f + (size_t)i2 * 32 + lane);
        uint2 v3 = __ldg(f + (size_t)i3 * 32 + lane);
        // pair-sum in fp16 (one extra rounding per pair), then fp32 accumulate
        __half2 p0 = __hadd2(*(__half2*)&v0.x, *(__half2*)&v1.x);
        __half2 p1 = __hadd2(*(__half2*)&v0.y, *(__half2*)&v1.y);
        __half2 q0 = __hadd2(*(__half2*)&v2.x, *(__half2*)&v3.x);
        __half2 q1 = __hadd2(*(__half2*)&v2.y, *(__half2*)&v3.y);
        float2 fp0 = __half22float2(p0);
        float2 fp1 = __half22float2(p1);
        float2 fq0 = __half22float2(q0);
        float2 fq1 = __half22float2(q1);
        acc.x += fp0.x + fq0.x;
        acc.y += fp0.y + fq0.y;
        acc.z += fp1.x + fq1.x;
        acc.w += fp1.y + fq1.y;
    }
    for (; e < s1; e++) {
        int a = g_esrc[e];
        uint2 va = __ldg(f + (size_t)a * 32 + lane);
        float2 fa0 = __half22float2(*(__half2*)&va.x);
        float2 fa1 = __half22float2(*(__half2*)&va.y);
        acc.x += fa0.x; acc.y += fa0.y; acc.z += fa1.x; acc.w += fa1.y;
    }
    float inv = 1.0f / fmaxf((float)(s1 - s0), 1.0f);
    uint2 o;
    *(__half2*)&o.x = __floats2half2_rn(acc.x * inv, acc.y * inv);
    *(__half2*)&o.y = __floats2half2_rn(acc.z * inv, acc.w * inv);
    ((uint2*)g_agg16)[(size_t)gw * 32 + lane] = o;
}

// ---------------- HMMA node transform ----------------
template<bool OUT_HALF>
__global__ void __launch_bounds__(256, 2)
mma_transform_k(const uint32_t* __restrict__ aggH,   // [m][64] half2-as-u32
                const uint32_t* __restrict__ selfH,
                const uint2* __restrict__ bfrag,     // 8192 x 8B fragments
                const float* __restrict__ bias,
                float* __restrict__ outF, __half2* __restrict__ outH,
                int nNodes, int ntiles) {
    extern __shared__ char smraw[];
    uint2* sB = (uint2*)smraw;                        // 64KB
    float* sBias = (float*)(smraw + 65536);
    int tid = threadIdx.x;
    for (int i = tid; i < 8192; i += 256) sB[i] = __ldg(bfrag + i);
    if (tid < 128) sBias[tid] = __ldg(bias + tid);
    __syncthreads();

    int warp = tid >> 5, lane = tid & 31;
    int r = lane >> 2, c = lane & 3;

    for (int tile = blockIdx.x; tile < ntiles; tile += gridDim.x) {
        int m0 = tile * 128 + warp * 16;
        size_t row0 = (size_t)min(m0 + r,     nNodes - 1);
        size_t row1 = (size_t)min(m0 + r + 8, nNodes - 1);
        const uint32_t* p0a = aggH  + row0 * 64 + c;
        const uint32_t* p1a = aggH  + row1 * 64 + c;
        const uint32_t* p0s = selfH + row0 * 64 + c;
        const uint32_t* p1s = selfH + row1 * 64 + c;

        float acc[16][4];
        #pragma unroll
        for (int nt = 0; nt < 16; nt++)
            #pragma unroll
            for (int q = 0; q < 4; q++) acc[nt][q] = 0.f;

        #pragma unroll
        for (int ks = 0; ks < 16; ks++) {
            const uint32_t* p0 = (ks < 8) ? p0a + ks * 8 : p0s + (ks - 8) * 8;
            const uint32_t* p1 = (ks < 8) ? p1a + ks * 8 : p1s + (ks - 8) * 8;
            uint32_t a0 = __ldg(p0), a2 = __ldg(p0 + 4);
            uint32_t a1 = __ldg(p1), a3 = __ldg(p1 + 4);
            const uint2* bp = sB + ks * 512 + lane;
            #pragma unroll
            for (int nt = 0; nt < 16; nt++) {
                uint2 b = bp[nt * 32];
                mma16816(acc[nt], a0, a1, a2, a3, b.x, b.y);
            }
        }

        bool ok0 = (m0 + r)     < nNodes;
        bool ok1 = (m0 + r + 8) < nNodes;
        #pragma unroll
        for (int nt = 0; nt < 16; nt++) {
            int j = nt * 8 + 2 * c;
            float b0 = sBias[j], b1 = sBias[j + 1];
            float v0 = acc[nt][0] + b0, v1 = acc[nt][1] + b1;
            float v2 = acc[nt][2] + b0, v3 = acc[nt][3] + b1;
            if (OUT_HALF) {
                if (ok0) outH[(size_t)(m0 + r)     * 64 + (j >> 1)] = __floats2half2_rn(v0, v1);
                if (ok1) outH[(size_t)(m0 + r + 8) * 64 + (j >> 1)] = __floats2half2_rn(v2, v3);
            } else {
                if (ok0) *(float2*)(outF + (size_t)(m0 + r)     * 128 + j) = make_float2(v0, v1);
                if (ok1) *(float2*)(outF + (size_t)(m0 + r + 8) * 128 + j) = make_float2(v2, v3);
            }
        }
    }
}

// ---------------- BN stats + finalize (last-block pattern) ----------------
__global__ void stats_k(const float* __restrict__ gamma,
                        const float* __restrict__ beta, float invN, int N) {
    int c2  = threadIdx.x & 63;
    int sub = threadIdx.x >> 6;      // 0..3
    float sx = 0.f, sy = 0.f, qx = 0.f, qy = 0.f;
    for (int row = blockIdx.x * 4 + sub; row < N; row += gridDim.x * 4) {
        float2 f = __half22float2(g_h16[(size_t)row * 64 + c2]);
        sx += f.x; sy += f.y; qx += f.x * f.x; qy += f.y * f.y;
    }
    red_add1(g_colsum   + 2 * c2,     sx);
    red_add1(g_colsum   + 2 * c2 + 1, sy);
    red_add1(g_colsumsq + 2 * c2,     qx);
    red_add1(g_colsumsq + 2 * c2 + 1, qy);
    __threadfence();
    __shared__ int isLast;
    __syncthreads();
    if (threadIdx.x == 0)
        isLast = (atomicAdd(&g_done, 1) == gridDim.x - 1);
    __syncthreads();
    if (isLast && threadIdx.x < 128) {
        int j = threadIdx.x;
        float mu  = __ldcg(g_colsum + j) * invN;
        float var = __ldcg(g_colsumsq + j) * invN - mu * mu;
        float sc  = __ldg(gamma + j) * rsqrtf(var + BN_EPS);
        g_scale[j] = sc;
        g_shift[j] = fmaf(-mu, sc, __ldg(beta + j));
    }
}

// ---------------- relu(bn(h)) in place on fp16 h ----------------
__global__ void relu_bn_k(int total2) {
    int i = blockIdx.x * blockDim.x + threadIdx.x;
    if (i >= total2) return;
    int c2 = i & 63;
    float2 sc = ((const float2*)g_scale)[c2];
    float2 sh = ((const float2*)g_shift)[c2];
    float2 f = __half22float2(g_h16[i]);
    f.x = fmaxf(fmaf(f.x, sc.x, sh.x), 0.f);
    f.y = fmaxf(fmaf(f.y, sc.y, sh.y), 0.f);
    g_h16[i] = __floats2half2_rn(f.x, f.y);
}

// ---------------- launch ----------------
extern "C" void kernel_launch(void* const* d_in, const int* in_sizes, int n_in,
                              void* d_out, int out_size) {
    const float* x     = (const float*)d_in[0];
    const int*   ei    = (const int*)d_in[1];     // int32
    const float* w1l   = (const float*)d_in[2];
    const float* b1l   = (const float*)d_in[3];
    const float* w1r   = (const float*)d_in[4];
    const float* w2l   = (const float*)d_in[5];
    const float* b2l   = (const float*)d_in[6];
    const float* w2r   = (const float*)d_in[7];
    const float* gamma = (const float*)d_in[8];
    const float* beta  = (const float*)d_in[9];
    float*       out   = (float*)d_out;

    int N = in_sizes[0] / D;
    int E = in_sizes[1] / 2;
    int ntiles = (N + 127) / 128;

    void *p_x16, *p_h16, *p_agg16, *p_bf1, *p_bf2;
    cudaGetSymbolAddress(&p_x16,   g_x16);
    cudaGetSymbolAddress(&p_h16,   g_h16);
    cudaGetSymbolAddress(&p_agg16, g_agg16);
    cudaGetSymbolAddress(&p_bf1,   g_bf1);
    cudaGetSymbolAddress(&p_bf2,   g_bf2);

    int smem = 65536 + 512;
    cudaFuncSetAttribute(mma_transform_k<true>,
                         cudaFuncAttributeMaxDynamicSharedMemorySize, smem);
    cudaFuncSetAttribute(mma_transform_k<false>,
                         cudaFuncAttributeMaxDynamicSharedMemorySize, smem);

    // fused setup: zeros (N+257 words) + 64 bfrag blocks + conv blocks
    int zb = (N + 257 + 255) / 256;
    int cb = (N * 32 + 255) / 256;
    setup_k<<<zb + 64 + cb, 256>>>(x, w1l, w1r, w2l, w2r, N, zb);

    // CSR build (reused by both layers); int4 path needs E % 4 == 0
    if ((E & 3) == 0) {
        int e4grid = (E / 4 + 255) / 256;
        hist4_k<<<e4grid, 256>>>(ei, E);
        scan_local_k<<<NBLK, SCAN_B>>>(N);
        scan_add_k<<<(N + 256) / 256, 256>>>(N, E);
        fill4_k<<<e4grid, 256>>>(ei, E);
    } else {
        int egrid = (E + 255) / 256;
        hist1_k<<<egrid, 256>>>(ei, E);
        scan_local_k<<<NBLK, SCAN_B>>>(N);
        scan_add_k<<<(N + 256) / 256, 256>>>(N, E);
        fill1_k<<<egrid, 256>>>(ei, E);
    }

    int ggrid = (N * 32 + 255) / 256;

    // layer 1: h = mean(x_nbr)@W1l + b1 + x@W1r   (fp16 inputs, fp32 acc)
    gather_k<<<ggrid, 256>>>((const __half2*)p_x16, N);
    mma_transform_k<true><<<TGRID, 256, smem>>>(
        (const uint32_t*)p_agg16, (const uint32_t*)p_x16,
        (const uint2*)p_bf1, b1l, nullptr, (__half2*)p_h16, N, ntiles);

    // BN stats + finalize (fused), then relu(bn(h)) in place
    stats_k<<<148, 256>>>(gamma, beta, 1.0f / (float)N, N);
    relu_bn_k<<<(N * 64 + 255) / 256, 256>>>(N * 64);

    // layer 2: out = mean(rbh_nbr)@W2l + b2 + rbh@W2r
    gather_k<<<ggrid, 256>>>((const __half2*)p_h16, N);
    mma_transform_k<false><<<TGRID, 256, smem>>>(
        (const uint32_t*)p_agg16, (const uint32_t*)p_h16,
        (const uint2*)p_bf2, b2l, out, nullptr, N, ntiles);
}

// round 14
// speedup vs baseline: 1.5686x; 1.0045x over previous
#include <cuda_runtime.h>
#include <cuda_fp16.h>
#include <cstdint>
#include <cstddef>

#define D 128
#define MAXN 50000
#define MAXE 800000
#define BN_EPS 1e-5f
#define SCAN_B 1024
#define TGRID 296                              // 2 persistent CTAs per SM

// ---------------- device scratch (zero-initialized at module load; every
// counter is restored to zero by its consumer for the next replay) --------------
__device__ __half2 g_x16[(size_t)MAXN * 64];    // fp16 x
__device__ __half2 g_h16[(size_t)MAXN * 64];    // fp16 h (relu(bn(h)) in place later)
__device__ __half2 g_agg16[(size_t)MAXN * 64];  // fp16 neighbor mean
__device__ __half2 g_bf1[16 * 16 * 32 * 2];     // layer-1 B fragments
__device__ __half2 g_bf2[16 * 16 * 32 * 2];     // layer-2 B fragments
__device__ int    g_cnt[MAXN];                  // zeroed by fill tail partition
__device__ int    g_offs[MAXN + 1];
__device__ int    g_cur[MAXN];
__device__ int    g_esrc[MAXE];
__device__ int    g_done;                       // zeroed by stats_k last block
__device__ float  g_colsum[D], g_colsumsq[D];   // zeroed by stats_k last block
__device__ float  g_scale[D], g_shift[D];

// ---------------- helpers ----------------
__device__ __forceinline__ void red_add1(float* p, float v) {
    asm volatile("red.global.add.f32 [%0], %1;" :: "l"(p), "f"(v) : "memory");
}
__device__ __forceinline__ void mma16816(float* c, uint32_t a0, uint32_t a1,
                                         uint32_t a2, uint32_t a3,
                                         uint32_t b0, uint32_t b1) {
    asm volatile("mma.sync.aligned.m16n8k16.row.col.f32.f16.f16.f32 "
                 "{%0,%1,%2,%3}, {%4,%5,%6,%7}, {%8,%9}, {%0,%1,%2,%3};"
                 : "+f"(c[0]), "+f"(c[1]), "+f"(c[2]), "+f"(c[3])
                 : "r"(a0), "r"(a1), "r"(a2), "r"(a3), "r"(b0), "r"(b1));
}

// ---------------- fused setup: conv x->fp16 + B fragments ----------------
// block partition: [0, 64) bfrag | [64, ...) conv
__global__ void setup_k(const float* __restrict__ x,
                        const float* __restrict__ w1l, const float* __restrict__ w1r,
                        const float* __restrict__ w2l, const float* __restrict__ w2r,
                        int N) {
    int b = blockIdx.x, t = threadIdx.x;
    if (b < 64) {
        // B fragment precompute: m16n8k16 B frag, lane t%32 holds
        // {B[k0+2(t%4)][n], B[k0+2(t%4)+1][n]} and same at k+8; n = nt*8 + t/4
        int idx = b * 256 + t;               // 0..16383
        int layer = idx >> 13;
        int slot  = idx & 8191;              // (ks*16+nt)*32 + lane
        int lane  = slot & 31;
        int fk    = slot >> 5;
        int ks = fk >> 4, nt = fk & 15;
        int n  = nt * 8 + (lane >> 2);
        int k0 = ks * 16 + 2 * (lane & 3);
        const float* wl = layer ? w2l : w1l;
        const float* wr = layer ? w2r : w1r;
        auto W = [&](int k) { return (k < 128) ? wl[n * 128 + k] : wr[n * 128 + k - 128]; };
        __half2* dst = (layer ? g_bf2 : g_bf1) + (size_t)slot * 2;
        dst[0] = __floats2half2_rn(W(k0),     W(k0 + 1));
        dst[1] = __floats2half2_rn(W(k0 + 8), W(k0 + 9));
        return;
    }
    int i = (b - 64) * 256 + t;              // float4 index over x
    if (i >= N * 32) return;
    float4 v = __ldg((const float4*)x + i);
    g_x16[(size_t)i * 2]     = __floats2half2_rn(v.x, v.y);
    g_x16[(size_t)i * 2 + 1] = __floats2half2_rn(v.z, v.w);
}

// ---------------- CSR build ----------------
// hist: 4 edges per thread via int4 (host guarantees E % 4 == 0 on this path)
__global__ void hist4_k(const int* __restrict__ ei, int E) {
    int i = blockIdx.x * blockDim.x + threadIdx.x;
    if (i * 4 >= E) return;
    int4 d = __ldg((const int4*)(ei + E) + i);
    atomicAdd(&g_cnt[d.x], 1);
    atomicAdd(&g_cnt[d.y], 1);
    atomicAdd(&g_cnt[d.z], 1);
    atomicAdd(&g_cnt[d.w], 1);
}
__global__ void hist1_k(const int* __restrict__ ei, int E) {
    int e = blockIdx.x * blockDim.x + threadIdx.x;
    if (e < E) atomicAdd(&g_cnt[ei[E + e]], 1);
}

// merged scan: each block redundantly sums counts of ALL preceding blocks
// (spread across 1024 threads; no cross-block dependency), then local scan.
__global__ void __launch_bounds__(1024, 1)
scan_k(int n, int E) {
    __shared__ int sm[SCAN_B];
    __shared__ int sRed[32];
    __shared__ int sPre;
    int b = blockIdx.x, t = threadIdx.x;
    int lane = t & 31, wid = t >> 5;

    // global prefix for this block: sum g_cnt[0 .. b*1024)
    int lim = b << 10;
    int pre = 0;
    for (int i = t; i < lim; i += SCAN_B) pre += g_cnt[i];
    #pragma unroll
    for (int off = 16; off; off >>= 1)
        pre += __shfl_down_sync(0xffffffffu, pre, off);
    if (lane == 0) sRed[wid] = pre;
    __syncthreads();
    if (wid == 0) {
        int v = sRed[lane];
        #pragma unroll
        for (int off = 16; off; off >>= 1)
            v += __shfl_down_sync(0xffffffffu, v, off);
        if (lane == 0) sPre = v;
    }

    // local exclusive scan of this block's 1024 counts
    int i = lim + t;
    int v = (i < n) ? g_cnt[i] : 0;
    sm[t] = v;
    __syncthreads();                 // also makes sPre visible
    int acc = v;
    #pragma unroll
    for (int off = 1; off < SCAN_B; off <<= 1) {
        int add = (t >= off) ? sm[t - off] : 0;
        __syncthreads();
        acc += add; sm[t] = acc;
        __syncthreads();
    }
    if (i < n) {
        int o = sPre + acc - v;
        g_offs[i] = o;
        g_cur[i] = o;
    }
    if (b == (int)gridDim.x - 1 && t == 0) g_offs[n] = E;
}

// fill: 4 edges per thread via int4; tail partition zeroes g_cnt for next replay
__global__ void fill4_k(const int* __restrict__ ei, int E, int e4b, int n) {
    if ((int)blockIdx.x < e4b) {
        int i = blockIdx.x * 256 + threadIdx.x;
        if (i * 4 >= E) return;
        int4 s = __ldg((const int4*)ei + i);
        int4 d = __ldg((const int4*)(ei + E) + i);
        g_esrc[atomicAdd(&g_cur[d.x], 1)] = s.x;
        g_esrc[atomicAdd(&g_cur[d.y], 1)] = s.y;
        g_esrc[atomicAdd(&g_cur[d.z], 1)] = s.z;
        g_esrc[atomicAdd(&g_cur[d.w], 1)] = s.w;
    } else {
        int i = (blockIdx.x - e4b) * 256 + threadIdx.x;
        if (i < n) g_cnt[i] = 0;
    }
}
__global__ void fill1_k(const int* __restrict__ ei, int E, int e1b, int n) {
    if ((int)blockIdx.x < e1b) {
        int e = blockIdx.x * 256 + threadIdx.x;
        if (e < E) {
            int d = ei[E + e];
            int pos = atomicAdd(&g_cur[d], 1);
            g_esrc[pos] = ei[e];
        }
    } else {
        int i = (blockIdx.x - e1b) * 256 + threadIdx.x;
        if (i < n) g_cnt[i] = 0;
    }
}

// ---------------- gather: one warp per node, 4-way ILP + fp16 pair-add ----------
__global__ void gather_k(const __half2* __restrict__ feat, int N) {
    int gw = (blockIdx.x * blockDim.x + threadIdx.x) >> 5;
    int lane = threadIdx.x & 31;
    if (gw >= N) return;
    int s0 = g_offs[gw], s1 = g_offs[gw + 1];
    const uint2* f = (const uint2*)feat;            // row = 32 uint2 (256B)
    float4 acc = make_float4(0.f, 0.f, 0.f, 0.f);
    int e = s0;
    for (; e + 4 <= s1; e += 4) {
        int i0 = g_esrc[e],     i1 = g_esrc[e + 1];
        int i2 = g_esrc[e + 2], i3 = g_esrc[e + 3];
        uint2 v0 = __ldg(f + (size_t)i0 * 32 + lane);
        uint2 v1 = __ldg(f + (size_t)i1 * 32 + lane);
        uint2 v2 = __ldg(f + (size_t)i2 * 32 + lane);
        uint2 v3 = __ldg(f + (size_t)i3 * 32 + lane);
        __half2 p0 = __hadd2(*(__half2*)&v0.x, *(__half2*)&v1.x);
        __half2 p1 = __hadd2(*(__half2*)&v0.y, *(__half2*)&v1.y);
        __half2 q0 = __hadd2(*(__half2*)&v2.x, *(__half2*)&v3.x);
        __half2 q1 = __hadd2(*(__half2*)&v2.y, *(__half2*)&v3.y);
        float2 fp0 = __half22float2(p0);
        float2 fp1 = __half22float2(p1);
        float2 fq0 = __half22float2(q0);
        float2 fq1 = __half22float2(q1);
        acc.x += fp0.x + fq0.x;
        acc.y += fp0.y + fq0.y;
        acc.z += fp1.x + fq1.x;
        acc.w += fp1.y + fq1.y;
    }
    for (; e < s1; e++) {
        int a = g_esrc[e];
        uint2 va = __ldg(f + (size_t)a * 32 + lane);
        float2 fa0 = __half22float2(*(__half2*)&va.x);
        float2 fa1 = __half22float2(*(__half2*)&va.y);
        acc.x += fa0.x; acc.y += fa0.y; acc.z += fa1.x; acc.w += fa1.y;
    }
    float inv = 1.0f / fmaxf((float)(s1 - s0), 1.0f);
    uint2 o;
    *(__half2*)&o.x = __floats2half2_rn(acc.x * inv, acc.y * inv);
    *(__half2*)&o.y = __floats2half2_rn(acc.z * inv, acc.w * inv);
    ((uint2*)g_agg16)[(size_t)gw * 32 + lane] = o;
}

// ---------------- HMMA node transform ----------------
template<bool OUT_HALF>
__global__ void __launch_bounds__(256, 2)
mma_transform_k(const uint32_t* __restrict__ aggH,   // [m][64] half2-as-u32
                const uint32_t* __restrict__ selfH,
                const uint2* __restrict__ bfrag,     // 8192 x 8B fragments
                const float* __restrict__ bias,
                float* __restrict__ outF, __half2* __restrict__ outH,
                int nNodes, int ntiles) {
    extern __shared__ char smraw[];
    uint2* sB = (uint2*)smraw;                        // 64KB
    float* sBias = (float*)(smraw + 65536);
    int tid = threadIdx.x;
    for (int i = tid; i < 8192; i += 256) sB[i] = __ldg(bfrag + i);
    if (tid < 128) sBias[tid] = __ldg(bias + tid);
    __syncthreads();

    int warp = tid >> 5, lane = tid & 31;
    int r = lane >> 2, c = lane & 3;

    for (int tile = blockIdx.x; tile < ntiles; tile += gridDim.x) {
        int m0 = tile * 128 + warp * 16;
        size_t row0 = (size_t)min(m0 + r,     nNodes - 1);
        size_t row1 = (size_t)min(m0 + r + 8, nNodes - 1);
        const uint32_t* p0a = aggH  + row0 * 64 + c;
        const uint32_t* p1a = aggH  + row1 * 64 + c;
        const uint32_t* p0s = selfH + row0 * 64 + c;
        const uint32_t* p1s = selfH + row1 * 64 + c;

        float acc[16][4];
        #pragma unroll
        for (int nt = 0; nt < 16; nt++)
            #pragma unroll
            for (int q = 0; q < 4; q++) acc[nt][q] = 0.f;

        #pragma unroll
        for (int ks = 0; ks < 16; ks++) {
            const uint32_t* p0 = (ks < 8) ? p0a + ks * 8 : p0s + (ks - 8) * 8;
            const uint32_t* p1 = (ks < 8) ? p1a + ks * 8 : p1s + (ks - 8) * 8;
            uint32_t a0 = __ldg(p0), a2 = __ldg(p0 + 4);
            uint32_t a1 = __ldg(p1), a3 = __ldg(p1 + 4);
            const uint2* bp = sB + ks * 512 + lane;
            #pragma unroll
            for (int nt = 0; nt < 16; nt++) {
                uint2 b = bp[nt * 32];
                mma16816(acc[nt], a0, a1, a2, a3, b.x, b.y);
            }
        }

        bool ok0 = (m0 + r)     < nNodes;
        bool ok1 = (m0 + r + 8) < nNodes;
        #pragma unroll
        for (int nt = 0; nt < 16; nt++) {
            int j = nt * 8 + 2 * c;
            float b0 = sBias[j], b1 = sBias[j + 1];
            float v0 = acc[nt][0] + b0, v1 = acc[nt][1] + b1;
            float v2 = acc[nt][2] + b0, v3 = acc[nt][3] + b1;
            if (OUT_HALF) {
                if (ok0) outH[(size_t)(m0 + r)     * 64 + (j >> 1)] = __floats2half2_rn(v0, v1);
                if (ok1) outH[(size_t)(m0 + r + 8) * 64 + (j >> 1)] = __floats2half2_rn(v2, v3);
            } else {
                if (ok0) *(float2*)(outF + (size_t)(m0 + r)     * 128 + j) = make_float2(v0, v1);
                if (ok1) *(float2*)(outF + (size_t)(m0 + r + 8) * 128 + j) = make_float2(v2, v3);
            }
        }
    }
}

// ---------------- BN stats + finalize (last-block), self-resetting --------------
__global__ void stats_k(const float* __restrict__ gamma,
                        const float* __restrict__ beta, float invN, int N) {
    int c2  = threadIdx.x & 63;
    int sub = threadIdx.x >> 6;      // 0..3
    float sx = 0.f, sy = 0.f, qx = 0.f, qy = 0.f;
    for (int row = blockIdx.x * 4 + sub; row < N; row += gridDim.x * 4) {
        float2 f = __half22float2(g_h16[(size_t)row * 64 + c2]);
        sx += f.x; sy += f.y; qx += f.x * f.x; qy += f.y * f.y;
    }
    red_add1(g_colsum   + 2 * c2,     sx);
    red_add1(g_colsum   + 2 * c2 + 1, sy);
    red_add1(g_colsumsq + 2 * c2,     qx);
    red_add1(g_colsumsq + 2 * c2 + 1, qy);
    __threadfence();
    __shared__ int isLast;
    __syncthreads();
    if (threadIdx.x == 0)
        isLast = (atomicAdd(&g_done, 1) == gridDim.x - 1);
    __syncthreads();
    if (isLast && threadIdx.x < 128) {
        int j = threadIdx.x;
        float mu  = __ldcg(g_colsum + j) * invN;
        float var = __ldcg(g_colsumsq + j) * invN - mu * mu;
        float sc  = __ldg(gamma + j) * rsqrtf(var + BN_EPS);
        g_scale[j] = sc;
        g_shift[j] = fmaf(-mu, sc, __ldg(beta + j));
        g_colsum[j] = 0.f;           // reset for next replay
        g_colsumsq[j] = 0.f;
        if (j == 0) g_done = 0;
    }
}

// ---------------- relu(bn(h)) in place on fp16 h ----------------
__global__ void relu_bn_k(int total2) {
    int i = blockIdx.x * blockDim.x + threadIdx.x;
    if (i >= total2) return;
    int c2 = i & 63;
    float2 sc = ((const float2*)g_scale)[c2];
    float2 sh = ((const float2*)g_shift)[c2];
    float2 f = __half22float2(g_h16[i]);
    f.x = fmaxf(fmaf(f.x, sc.x, sh.x), 0.f);
    f.y = fmaxf(fmaf(f.y, sc.y, sh.y), 0.f);
    g_h16[i] = __floats2half2_rn(f.x, f.y);
}

// ---------------- launch ----------------
extern "C" void kernel_launch(void* const* d_in, const int* in_sizes, int n_in,
                              void* d_out, int out_size) {
    const float* x     = (const float*)d_in[0];
    const int*   ei    = (const int*)d_in[1];     // int32
    const float* w1l   = (const float*)d_in[2];
    const float* b1l   = (const float*)d_in[3];
    const float* w1r   = (const float*)d_in[4];
    const float* w2l   = (const float*)d_in[5];
    const float* b2l   = (const float*)d_in[6];
    const float* w2r   = (const float*)d_in[7];
    const float* gamma = (const float*)d_in[8];
    const float* beta  = (const float*)d_in[9];
    float*       out   = (float*)d_out;

    int N = in_sizes[0] / D;
    int E = in_sizes[1] / 2;
    int ntiles = (N + 127) / 128;
    int nblk = (N + SCAN_B - 1) / SCAN_B;
    int nzb = (N + 255) / 256;

    void *p_x16, *p_h16, *p_agg16, *p_bf1, *p_bf2;
    cudaGetSymbolAddress(&p_x16,   g_x16);
    cudaGetSymbolAddress(&p_h16,   g_h16);
    cudaGetSymbolAddress(&p_agg16, g_agg16);
    cudaGetSymbolAddress(&p_bf1,   g_bf1);
    cudaGetSymbolAddress(&p_bf2,   g_bf2);

    int smem = 65536 + 512;
    cudaFuncSetAttribute(mma_transform_k<true>,
                         cudaFuncAttributeMaxDynamicSharedMemorySize, smem);
    cudaFuncSetAttribute(mma_transform_k<false>,
                         cudaFuncAttributeMaxDynamicSharedMemorySize, smem);

    // fused setup: 64 bfrag blocks + conv blocks (counters self-reset elsewhere)
    int cb = (N * 32 + 255) / 256;
    setup_k<<<64 + cb, 256>>>(x, w1l, w1r, w2l, w2r, N);

    // CSR build (reused by both layers); int4 path needs E % 4 == 0
    if ((E & 3) == 0) {
        int e4b = (E / 4 + 255) / 256;
        hist4_k<<<e4b, 256>>>(ei, E);
        scan_k<<<nblk, SCAN_B>>>(N, E);
        fill4_k<<<e4b + nzb, 256>>>(ei, E, e4b, N);
    } else {
        int e1b = (E + 255) / 256;
        hist1_k<<<e1b, 256>>>(ei, E);
        scan_k<<<nblk, SCAN_B>>>(N, E);
        fill1_k<<<e1b + nzb, 256>>>(ei, E, e1b, N);
    }

    int ggrid = (N * 32 + 255) / 256;

    // layer 1: h = mean(x_nbr)@W1l + b1 + x@W1r   (fp16 inputs, fp32 acc)
    gather_k<<<ggrid, 256>>>((const __half2*)p_x16, N);
    mma_transform_k<true><<<TGRID, 256, smem>>>(
        (const uint32_t*)p_agg16, (const uint32_t*)p_x16,
        (const uint2*)p_bf1, b1l, nullptr, (__half2*)p_h16, N, ntiles);

    // BN stats + finalize (fused, self-resetting), then relu(bn(h)) in place
    stats_k<<<148, 256>>>(gamma, beta, 1.0f / (float)N, N);
    relu_bn_k<<<(N * 64 + 255) / 256, 256>>>(N * 64);

    // layer 2: out = mean(rbh_nbr)@W2l + b2 + rbh@W2r
    gather_k<<<ggrid, 256>>>((const __half2*)p_h16, N);
    mma_transform_k<false><<<TGRID, 256, smem>>>(
        (const uint32_t*)p_agg16, (const uint32_t*)p_h16,
        (const uint2*)p_bf2, b2l, out, nullptr, N, ntiles);
}

// round 16
// speedup vs baseline: 1.8917x; 1.2059x over previous
#include <cuda_runtime.h>
#include <cuda_fp16.h>
#include <cstdint>
#include <cstddef>

#define D 128
#define MAXN 50000
#define MAXE 800000
#define BN_EPS 1e-5f
#define SCAN_B 1024
#define TGRID 296                              // 2 persistent CTAs per SM

// smem layout for transform: sB 64KB | sBias 512B | sStat 8KB (8 warps x 256 f32)
#define SMEM_T (65536 + 512 + 8192)

// ---------------- device scratch (zero-initialized at module load; every
// counter is restored to zero by its consumer for the next replay) --------------
__device__ __half2 g_x16[(size_t)MAXN * 64];    // fp16 x
__device__ __half2 g_h16[(size_t)MAXN * 64];    // fp16 h (relu(bn(h)) in place later)
__device__ __half2 g_agg16[(size_t)MAXN * 64];  // fp16 neighbor mean
__device__ __half2 g_bf1[16 * 16 * 32 * 2];     // layer-1 B fragments
__device__ __half2 g_bf2[16 * 16 * 32 * 2];     // layer-2 B fragments
__device__ int    g_cnt[MAXN];                  // zeroed by fill tail partition
__device__ int    g_offs[MAXN + 1];
__device__ int    g_cur[MAXN];
__device__ int    g_esrc[MAXE];
__device__ int    g_done;                       // zeroed by transform1 last block
__device__ float  g_colsum[D], g_colsumsq[D];   // zeroed by transform1 last block
__device__ float  g_scale[D], g_shift[D];

// ---------------- helpers ----------------
__device__ __forceinline__ void red_add1(float* p, float v) {
    asm volatile("red.global.add.f32 [%0], %1;" :: "l"(p), "f"(v) : "memory");
}
__device__ __forceinline__ void mma16816(float* c, uint32_t a0, uint32_t a1,
                                         uint32_t a2, uint32_t a3,
                                         uint32_t b0, uint32_t b1) {
    asm volatile("mma.sync.aligned.m16n8k16.row.col.f32.f16.f16.f32 "
                 "{%0,%1,%2,%3}, {%4,%5,%6,%7}, {%8,%9}, {%0,%1,%2,%3};"
                 : "+f"(c[0]), "+f"(c[1]), "+f"(c[2]), "+f"(c[3])
                 : "r"(a0), "r"(a1), "r"(a2), "r"(a3), "r"(b0), "r"(b1));
}

// ---------------- fused setup: B fragments + conv x->fp16 + degree histogram ----
// block partition: [0, 64) bfrag | [64, 64+cb) conv | [64+cb, ...) hist
__global__ void setup_k(const float* __restrict__ x,
                        const float* __restrict__ w1l, const float* __restrict__ w1r,
                        const float* __restrict__ w2l, const float* __restrict__ w2r,
                        const int* __restrict__ ei, int N, int E, int cb, int vec4) {
    int b = blockIdx.x, t = threadIdx.x;
    if (b < 64) {
        // B fragment precompute: m16n8k16 B frag, lane t%32 holds
        // {B[k0+2(t%4)][n], B[k0+2(t%4)+1][n]} and same at k+8; n = nt*8 + t/4
        int idx = b * 256 + t;               // 0..16383
        int layer = idx >> 13;
        int slot  = idx & 8191;              // (ks*16+nt)*32 + lane
        int lane  = slot & 31;
        int fk    = slot >> 5;
        int ks = fk >> 4, nt = fk & 15;
        int n  = nt * 8 + (lane >> 2);
        int k0 = ks * 16 + 2 * (lane & 3);
        const float* wl = layer ? w2l : w1l;
        const float* wr = layer ? w2r : w1r;
        auto W = [&](int k) { return (k < 128) ? wl[n * 128 + k] : wr[n * 128 + k - 128]; };
        __half2* dst = (layer ? g_bf2 : g_bf1) + (size_t)slot * 2;
        dst[0] = __floats2half2_rn(W(k0),     W(k0 + 1));
        dst[1] = __floats2half2_rn(W(k0 + 8), W(k0 + 9));
        return;
    }
    if (b < 64 + cb) {
        int i = (b - 64) * 256 + t;          // float4 index over x
        if (i >= N * 32) return;
        float4 v = __ldg((const float4*)x + i);
        g_x16[(size_t)i * 2]     = __floats2half2_rn(v.x, v.y);
        g_x16[(size_t)i * 2 + 1] = __floats2half2_rn(v.z, v.w);
        return;
    }
    // histogram partition
    if (vec4) {
        int i = (b - 64 - cb) * 256 + t;
        if (i * 4 >= E) return;
        int4 d = __ldg((const int4*)(ei + E) + i);
        atomicAdd(&g_cnt[d.x], 1);
        atomicAdd(&g_cnt[d.y], 1);
        atomicAdd(&g_cnt[d.z], 1);
        atomicAdd(&g_cnt[d.w], 1);
    } else {
        int e = (b - 64 - cb) * 256 + t;
        if (e < E) atomicAdd(&g_cnt[ei[E + e]], 1);
    }
}

// merged scan: each block redundantly sums counts of ALL preceding blocks
// (spread across 1024 threads; no cross-block dependency), then local scan.
__global__ void __launch_bounds__(1024, 1)
scan_k(int n, int E) {
    __shared__ int sm[SCAN_B];
    __shared__ int sRed[32];
    __shared__ int sPre;
    int b = blockIdx.x, t = threadIdx.x;
    int lane = t & 31, wid = t >> 5;

    int lim = b << 10;
    int pre = 0;
    for (int i = t; i < lim; i += SCAN_B) pre += g_cnt[i];
    #pragma unroll
    for (int off = 16; off; off >>= 1)
        pre += __shfl_down_sync(0xffffffffu, pre, off);
    if (lane == 0) sRed[wid] = pre;
    __syncthreads();
    if (wid == 0) {
        int v = sRed[lane];
        #pragma unroll
        for (int off = 16; off; off >>= 1)
            v += __shfl_down_sync(0xffffffffu, v, off);
        if (lane == 0) sPre = v;
    }

    int i = lim + t;
    int v = (i < n) ? g_cnt[i] : 0;
    sm[t] = v;
    __syncthreads();
    int acc = v;
    #pragma unroll
    for (int off = 1; off < SCAN_B; off <<= 1) {
        int add = (t >= off) ? sm[t - off] : 0;
        __syncthreads();
        acc += add; sm[t] = acc;
        __syncthreads();
    }
    if (i < n) {
        int o = sPre + acc - v;
        g_offs[i] = o;
        g_cur[i] = o;
    }
    if (b == (int)gridDim.x - 1 && t == 0) g_offs[n] = E;
}

// fill: 4 edges per thread via int4; tail partition zeroes g_cnt for next replay
__global__ void fill4_k(const int* __restrict__ ei, int E, int e4b, int n) {
    if ((int)blockIdx.x < e4b) {
        int i = blockIdx.x * 256 + threadIdx.x;
        if (i * 4 >= E) return;
        int4 s = __ldg((const int4*)ei + i);
        int4 d = __ldg((const int4*)(ei + E) + i);
        g_esrc[atomicAdd(&g_cur[d.x], 1)] = s.x;
        g_esrc[atomicAdd(&g_cur[d.y], 1)] = s.y;
        g_esrc[atomicAdd(&g_cur[d.z], 1)] = s.z;
        g_esrc[atomicAdd(&g_cur[d.w], 1)] = s.w;
    } else {
        int i = (blockIdx.x - e4b) * 256 + threadIdx.x;
        if (i < n) g_cnt[i] = 0;
    }
}
__global__ void fill1_k(const int* __restrict__ ei, int E, int e1b, int n) {
    if ((int)blockIdx.x < e1b) {
        int e = blockIdx.x * 256 + threadIdx.x;
        if (e < E) {
            int d = ei[E + e];
            int pos = atomicAdd(&g_cur[d], 1);
            g_esrc[pos] = ei[e];
        }
    } else {
        int i = (blockIdx.x - e1b) * 256 + threadIdx.x;
        if (i < n) g_cnt[i] = 0;
    }
}

// ---------------- gather: one warp per node, 4-way ILP + fp16 pair-add ----------
__global__ void gather_k(const __half2* __restrict__ feat, int N) {
    int gw = (blockIdx.x * blockDim.x + threadIdx.x) >> 5;
    int lane = threadIdx.x & 31;
    if (gw >= N) return;
    int s0 = g_offs[gw], s1 = g_offs[gw + 1];
    const uint2* f = (const uint2*)feat;            // row = 32 uint2 (256B)
    float4 acc = make_float4(0.f, 0.f, 0.f, 0.f);
    int e = s0;
    for (; e + 4 <= s1; e += 4) {
        int i0 = g_esrc[e],     i1 = g_esrc[e + 1];
        int i2 = g_esrc[e + 2], i3 = g_esrc[e + 3];
        uint2 v0 = __ldg(f + (size_t)i0 * 32 + lane);
        uint2 v1 = __ldg(f + (size_t)i1 * 32 + lane);
        uint2 v2 = __ldg(f + (size_t)i2 * 32 + lane);
        uint2 v3 = __ldg(f + (size_t)i3 * 32 + lane);
        __half2 p0 = __hadd2(*(__half2*)&v0.x, *(__half2*)&v1.x);
        __half2 p1 = __hadd2(*(__half2*)&v0.y, *(__half2*)&v1.y);
        __half2 q0 = __hadd2(*(__half2*)&v2.x, *(__half2*)&v3.x);
        __half2 q1 = __hadd2(*(__half2*)&v2.y, *(__half2*)&v3.y);
        float2 fp0 = __half22float2(p0);
        float2 fp1 = __half22float2(p1);
        float2 fq0 = __half22float2(q0);
        float2 fq1 = __half22float2(q1);
        acc.x += fp0.x + fq0.x;
        acc.y += fp0.y + fq0.y;
        acc.z += fp1.x + fq1.x;
        acc.w += fp1.y + fq1.y;
    }
    for (; e < s1; e++) {
        int a = g_esrc[e];
        uint2 va = __ldg(f + (size_t)a * 32 + lane);
        float2 fa0 = __half22float2(*(__half2*)&va.x);
        float2 fa1 = __half22float2(*(__half2*)&va.y);
        acc.x += fa0.x; acc.y += fa0.y; acc.z += fa1.x; acc.w += fa1.y;
    }
    float inv = 1.0f / fmaxf((float)(s1 - s0), 1.0f);
    uint2 o;
    *(__half2*)&o.x = __floats2half2_rn(acc.x * inv, acc.y * inv);
    *(__half2*)&o.y = __floats2half2_rn(acc.z * inv, acc.w * inv);
    ((uint2*)g_agg16)[(size_t)gw * 32 + lane] = o;
}

// ---------------- HMMA node transform (+ fused BN stats for layer 1) -------------
// STATS=true: write h as fp16 AND accumulate per-column sum/sumsq (pre-rounding
// fp32 values) via shfl-reduce + per-warp smem; last block finalizes scale/shift.
template<bool STATS>
__global__ void __launch_bounds__(256, 2)
mma_transform_k(const uint32_t* __restrict__ aggH,   // [m][64] half2-as-u32
                const uint32_t* __restrict__ selfH,
                const uint2* __restrict__ bfrag,     // 8192 x 8B fragments
                const float* __restrict__ bias,
                float* __restrict__ outF, __half2* __restrict__ outH,
                const float* __restrict__ gamma, const float* __restrict__ beta,
                float invN, int nNodes, int ntiles) {
    extern __shared__ char smraw[];
    uint2* sB = (uint2*)smraw;                        // 64KB
    float* sBias = (float*)(smraw + 65536);
    float* sStat = (float*)(smraw + 65536 + 512);     // [8 warps][256]
    int tid = threadIdx.x;
    for (int i = tid; i < 8192; i += 256) sB[i] = __ldg(bfrag + i);
    if (tid < 128) sBias[tid] = __ldg(bias + tid);
    if (STATS) {
        #pragma unroll
        for (int i = 0; i < 8; i++) sStat[tid + i * 256] = 0.f;
    }
    __syncthreads();

    int warp = tid >> 5, lane = tid & 31;
    int r = lane >> 2, c = lane & 3;
    float* wStat = sStat + warp * 256;    // [0..127]=sum, [128..255]=sumsq

    for (int tile = blockIdx.x; tile < ntiles; tile += gridDim.x) {
        int m0 = tile * 128 + warp * 16;
        size_t row0 = (size_t)min(m0 + r,     nNodes - 1);
        size_t row1 = (size_t)min(m0 + r + 8, nNodes - 1);
        const uint32_t* p0a = aggH  + row0 * 64 + c;
        const uint32_t* p1a = aggH  + row1 * 64 + c;
        const uint32_t* p0s = selfH + row0 * 64 + c;
        const uint32_t* p1s = selfH + row1 * 64 + c;

        float acc[16][4];
        #pragma unroll
        for (int nt = 0; nt < 16; nt++)
            #pragma unroll
            for (int q = 0; q < 4; q++) acc[nt][q] = 0.f;

        #pragma unroll
        for (int ks = 0; ks < 16; ks++) {
            const uint32_t* p0 = (ks < 8) ? p0a + ks * 8 : p0s + (ks - 8) * 8;
            const uint32_t* p1 = (ks < 8) ? p1a + ks * 8 : p1s + (ks - 8) * 8;
            uint32_t a0 = __ldg(p0), a2 = __ldg(p0 + 4);
            uint32_t a1 = __ldg(p1), a3 = __ldg(p1 + 4);
            const uint2* bp = sB + ks * 512 + lane;
            #pragma unroll
            for (int nt = 0; nt < 16; nt++) {
                uint2 b = bp[nt * 32];
                mma16816(acc[nt], a0, a1, a2, a3, b.x, b.y);
            }
        }

        bool ok0 = (m0 + r)     < nNodes;
        bool ok1 = (m0 + r + 8) < nNodes;
        #pragma unroll
        for (int nt = 0; nt < 16; nt++) {
            int j = nt * 8 + 2 * c;
            float b0 = sBias[j], b1 = sBias[j + 1];
            float v0 = acc[nt][0] + b0, v1 = acc[nt][1] + b1;
            float v2 = acc[nt][2] + b0, v3 = acc[nt][3] + b1;
            if (STATS) {
                if (ok0) outH[(size_t)(m0 + r)     * 64 + (j >> 1)] = __floats2half2_rn(v0, v1);
                if (ok1) outH[(size_t)(m0 + r + 8) * 64 + (j >> 1)] = __floats2half2_rn(v2, v3);
                // per-column stats: reduce across the 8 row-lanes (same c)
                float sj  = (ok0 ? v0 : 0.f) + (ok1 ? v2 : 0.f);
                float sj1 = (ok0 ? v1 : 0.f) + (ok1 ? v3 : 0.f);
                float qj  = (ok0 ? v0 * v0 : 0.f) + (ok1 ? v2 * v2 : 0.f);
                float qj1 = (ok0 ? v1 * v1 : 0.f) + (ok1 ? v3 * v3 : 0.f);
                #pragma unroll
                for (int off = 16; off >= 4; off >>= 1) {
                    sj  += __shfl_down_sync(0xffffffffu, sj,  off);
                    sj1 += __shfl_down_sync(0xffffffffu, sj1, off);
                    qj  += __shfl_down_sync(0xffffffffu, qj,  off);
                    qj1 += __shfl_down_sync(0xffffffffu, qj1, off);
                }
                if (lane < 4) {       // r==0 lanes; c == lane
                    int jj = nt * 8 + 2 * lane;
                    wStat[jj]           += sj;
                    wStat[jj + 1]       += sj1;
                    wStat[128 + jj]     += qj;
                    wStat[128 + jj + 1] += qj1;
                }
            } else {
                if (ok0) *(float2*)(outF + (size_t)(m0 + r)     * 128 + j) = make_float2(v0, v1);
                if (ok1) *(float2*)(outF + (size_t)(m0 + r + 8) * 128 + j) = make_float2(v2, v3);
            }
        }
    }

    if (STATS) {
        __syncthreads();
        // block-reduce across 8 warps, one slot per thread, then RED to global
        float t = 0.f;
        #pragma unroll
        for (int w = 0; w < 8; w++) t += sStat[w * 256 + tid];
        if (tid < 128) red_add1(g_colsum + tid, t);
        else           red_add1(g_colsumsq + (tid - 128), t);
        __threadfence();
        __shared__ int isLast;
        __syncthreads();
        if (tid == 0) isLast = (atomicAdd(&g_done, 1) == gridDim.x - 1);
        __syncthreads();
        if (isLast && tid < 128) {
            int j = tid;
            float mu  = __ldcg(g_colsum + j) * invN;
            float var = __ldcg(g_colsumsq + j) * invN - mu * mu;
            float sc  = __ldg(gamma + j) * rsqrtf(var + BN_EPS);
            g_scale[j] = sc;
            g_shift[j] = fmaf(-mu, sc, __ldg(beta + j));
            g_colsum[j] = 0.f;       // reset for next replay
            g_colsumsq[j] = 0.f;
            if (j == 0) g_done = 0;
        }
    }
}

// ---------------- relu(bn(h)) in place on fp16 h ----------------
__global__ void relu_bn_k(int total2) {
    int i = blockIdx.x * blockDim.x + threadIdx.x;
    if (i >= total2) return;
    int c2 = i & 63;
    float2 sc = ((const float2*)g_scale)[c2];
    float2 sh = ((const float2*)g_shift)[c2];
    float2 f = __half22float2(g_h16[i]);
    f.x = fmaxf(fmaf(f.x, sc.x, sh.x), 0.f);
    f.y = fmaxf(fmaf(f.y, sc.y, sh.y), 0.f);
    g_h16[i] = __floats2half2_rn(f.x, f.y);
}

// ---------------- launch ----------------
extern "C" void kernel_launch(void* const* d_in, const int* in_sizes, int n_in,
                              void* d_out, int out_size) {
    const float* x     = (const float*)d_in[0];
    const int*   ei    = (const int*)d_in[1];     // int32
    const float* w1l   = (const float*)d_in[2];
    const float* b1l   = (const float*)d_in[3];
    const float* w1r   = (const float*)d_in[4];
    const float* w2l   = (const float*)d_in[5];
    const float* b2l   = (const float*)d_in[6];
    const float* w2r   = (const float*)d_in[7];
    const float* gamma = (const float*)d_in[8];
    const float* beta  = (const float*)d_in[9];
    float*       out   = (float*)d_out;

    int N = in_sizes[0] / D;
    int E = in_sizes[1] / 2;
    int ntiles = (N + 127) / 128;
    int nblk = (N + SCAN_B - 1) / SCAN_B;
    int nzb = (N + 255) / 256;
    int vec4 = ((E & 3) == 0) ? 1 : 0;

    void *p_x16, *p_h16, *p_agg16, *p_bf1, *p_bf2;
    cudaGetSymbolAddress(&p_x16,   g_x16);
    cudaGetSymbolAddress(&p_h16,   g_h16);
    cudaGetSymbolAddress(&p_agg16, g_agg16);
    cudaGetSymbolAddress(&p_bf1,   g_bf1);
    cudaGetSymbolAddress(&p_bf2,   g_bf2);

    cudaFuncSetAttribute(mma_transform_k<true>,
                         cudaFuncAttributeMaxDynamicSharedMemorySize, SMEM_T);
    cudaFuncSetAttribute(mma_transform_k<false>,
                         cudaFuncAttributeMaxDynamicSharedMemorySize, SMEM_T);

    // fused setup: 64 bfrag + cb conv + hb hist blocks
    int cb = (N * 32 + 255) / 256;
    int hb = vec4 ? (E / 4 + 255) / 256 : (E + 255) / 256;
    setup_k<<<64 + cb + hb, 256>>>(x, w1l, w1r, w2l, w2r, ei, N, E, cb, vec4);

    // CSR: merged scan, then fill (+ cnt reset tail)
    scan_k<<<nblk, SCAN_B>>>(N, E);
    if (vec4) fill4_k<<<hb + nzb, 256>>>(ei, E, hb, N);
    else      fill1_k<<<hb + nzb, 256>>>(ei, E, hb, N);

    int ggrid = (N * 32 + 255) / 256;

    // layer 1: h = mean(x_nbr)@W1l + b1 + x@W1r ; BN stats fused into epilogue
    gather_k<<<ggrid, 256>>>((const __half2*)p_x16, N);
    mma_transform_k<true><<<TGRID, 256, SMEM_T>>>(
        (const uint32_t*)p_agg16, (const uint32_t*)p_x16,
        (const uint2*)p_bf1, b1l, nullptr, (__half2*)p_h16,
        gamma, beta, 1.0f / (float)N, N, ntiles);

    // relu(bn(h)) in place
    relu_bn_k<<<(N * 64 + 255) / 256, 256>>>(N * 64);

    // layer 2: out = mean(rbh_nbr)@W2l + b2 + rbh@W2r
    gather_k<<<ggrid, 256>>>((const __half2*)p_h16, N);
    mma_transform_k<false><<<TGRID, 256, SMEM_T>>>(
        (const uint32_t*)p_agg16, (const uint32_t*)p_h16,
        (const uint2*)p_bf2, b2l, out, nullptr,
        nullptr, nullptr, 0.f, N, ntiles);
}